// round 11
// baseline (speedup 1.0000x reference)
#include <cuda_runtime.h>
#include <cuda_fp16.h>
#include <math.h>
#include <stdint.h>

// x: [B=16, C=64, F=40, T=512] fp32; Wq/Wk/Wv: [64,64] fp32
#define BATCH 16
#define CCH   64
#define FFREQ 40
#define TT    512
#define DDIM  2560
#define XBSTR ((long)DDIM * TT)
#define SBSTR ((long)TT * TT)

// -------- scratch --------
__device__ float  g_G  [CCH * CCH];
__device__ __half g_xrP[BATCH * DDIM * TT];    // h(x), [b][d=f*64+c][t]
__device__ __half g_uP [BATCH * DDIM * TT];    // h(scale * G∘x), [b][d][t]
__device__ __half g_p  [BATCH * TT * TT];      // P~ = exp(S), unnormalized
__device__ float  g_rs [BATCH * TT];           // row sums of P~

// ---------------- helpers ----------------
__device__ __forceinline__ uint32_t smem_u32(const void* p) {
    uint32_t a;
    asm("{ .reg .u64 t; cvta.to.shared.u64 t, %1; cvt.u32.u64 %0, t; }" : "=r"(a) : "l"(p));
    return a;
}
__device__ __forceinline__ void cp16(uint32_t sdst, const void* g) {
    asm volatile("cp.async.cg.shared.global [%0], [%1], 16;" :: "r"(sdst), "l"(g));
}
__device__ __forceinline__ void cp_commit() { asm volatile("cp.async.commit_group;"); }
__device__ __forceinline__ void cp_wait1()  { asm volatile("cp.async.wait_group 1;"); }
__device__ __forceinline__ uint32_t lds32(uint32_t a) {
    uint32_t v; asm volatile("ld.shared.b32 %0, [%1];" : "=r"(v) : "r"(a)); return v;
}
__device__ __forceinline__ float ldsf(uint32_t a) {
    float v; asm volatile("ld.shared.f32 %0, [%1];" : "=f"(v) : "r"(a)); return v;
}
__device__ __forceinline__ void sts16(uint32_t a, uint16_t v) {
    asm volatile("st.shared.u16 [%0], %1;" :: "r"(a), "h"(v));
}
__device__ __forceinline__ void sts32(uint32_t a, uint32_t v) {
    asm volatile("st.shared.b32 [%0], %1;" :: "r"(a), "r"(v));
}
__device__ __forceinline__ void sts64(uint32_t a, uint32_t x, uint32_t y) {
    asm volatile("st.shared.v2.b32 [%0], {%1, %2};" :: "r"(a), "r"(x), "r"(y));
}
__device__ __forceinline__ void ldsm4t(uint32_t& r0, uint32_t& r1, uint32_t& r2,
                                       uint32_t& r3, uint32_t addr) {
    asm volatile("ldmatrix.sync.aligned.m8n8.x4.trans.shared.b16 {%0,%1,%2,%3}, [%4];"
                 : "=r"(r0), "=r"(r1), "=r"(r2), "=r"(r3) : "r"(addr));
}
__device__ __forceinline__ void ldsm4(uint32_t& r0, uint32_t& r1, uint32_t& r2,
                                      uint32_t& r3, uint32_t addr) {
    asm volatile("ldmatrix.sync.aligned.m8n8.x4.shared.b16 {%0,%1,%2,%3}, [%4];"
                 : "=r"(r0), "=r"(r1), "=r"(r2), "=r"(r3) : "r"(addr));
}

#define MMA16816(d, a, b0, b1)                                                   \
    asm volatile(                                                                \
        "mma.sync.aligned.m16n8k16.row.col.f32.f16.f16.f32 "                     \
        "{%0,%1,%2,%3}, {%4,%5,%6,%7}, {%8,%9}, {%0,%1,%2,%3};"                  \
        : "+f"((d)[0]), "+f"((d)[1]), "+f"((d)[2]), "+f"((d)[3])                 \
        : "r"((a)[0]), "r"((a)[1]), "r"((a)[2]), "r"((a)[3]), "r"(b0), "r"(b1))

// ============================ G = Wq^T Wk ============================
__global__ void compute_G_kernel(const float* __restrict__ Wq,
                                 const float* __restrict__ Wk) {
    __shared__ float sq[CCH * CCH], sk[CCH * CCH];
    int tid = threadIdx.x;
    for (int i = tid; i < CCH * CCH; i += blockDim.x) { sq[i] = Wq[i]; sk[i] = Wk[i]; }
    __syncthreads();
    for (int i = tid; i < CCH * CCH; i += blockDim.x) {
        int c = i / CCH, cp = i % CCH;
        float acc = 0.f;
        #pragma unroll 16
        for (int o = 0; o < CCH; o++) acc += sq[o * CCH + c] * sk[o * CCH + cp];
        g_G[i] = acc;
    }
}

// -------- zero row sums --------
__global__ void zero_rs_kernel() {
    g_rs[blockIdx.x * 256 + threadIdx.x] = 0.f;
}

// ======== prep: x -> xrP [d][t] AND uP = h(scale * G@x) [d][t] ========
__global__ void __launch_bounds__(256)
prep_kernel(const float* __restrict__ x, float scale) {
    __shared__ __align__(128) char sm[24576];
    const uint32_t xh = smem_u32(sm);            // [c'][t] half, 256B rows, swz16
    const uint32_t gg = xh + 16384;              // [c][c'] half, 128B rows, swz16
    const int t0 = blockIdx.x * 128;
    const int f  = blockIdx.y;
    const int b  = blockIdx.z;
    const float* xb = x + (long)b * XBSTR;
    __half* xrP = g_xrP + (long)b * XBSTR;
    __half* uP  = g_uP  + (long)b * XBSTR;
    const int tid = threadIdx.x;

    #pragma unroll
    for (int i = 0; i < 8; i++) {
        int idx = tid + 256 * i;
        int c = idx >> 5, q = idx & 31;
        float4 v = *(const float4*)&xb[((long)c * FFREQ + f) * TT + t0 + q * 4];
        __half2 h0 = __floats2half2_rn(v.x, v.y);
        __half2 h1 = __floats2half2_rn(v.z, v.w);
        *(uint2*)&xrP[((long)f * CCH + c) * TT + t0 + q * 4] =
            make_uint2(*(uint32_t*)&h0, *(uint32_t*)&h1);
        uint32_t ad = xh + c * 256 + ((((q >> 1) ^ (c & 7)) << 4)) + ((q & 1) * 8);
        sts64(ad, *(uint32_t*)&h0, *(uint32_t*)&h1);
    }
    #pragma unroll
    for (int i = 0; i < 16; i++) {
        int idx = tid + 256 * i;
        int m = idx >> 6, k = idx & 63;
        sts16(gg + m * 128 + (((k >> 3) ^ (m & 7)) << 4) + ((k & 7) * 2),
              __half_as_ushort(__float2half_rn(g_G[m * CCH + k])));
    }
    __syncthreads();

    const int w = tid >> 5, lane = tid & 31, grp = lane >> 2, tig = lane & 3;
    const int wm = (w & 1) * 32, wn = (w >> 1) * 32;
    float acc[2][4][4] = {};
    #pragma unroll
    for (int ks = 0; ks < 4; ks++) {
        const int off = 4 * tig, ch0 = 2 * ks;
        const uint32_t x0 = ((ch0 ^ grp) << 4), x1 = (((ch0 + 1) ^ grp) << 4);
        uint32_t a[2][4], bfr[4][2];
        #pragma unroll
        for (int i = 0; i < 2; i++) {
            uint32_t b0 = gg + (wm + i * 16 + grp) * 128 + off;
            uint32_t b1 = b0 + 1024;
            a[i][0] = lds32(b0 + x0); a[i][1] = lds32(b1 + x0);
            a[i][2] = lds32(b0 + x1); a[i][3] = lds32(b1 + x1);
        }
        #pragma unroll
        for (int j2 = 0; j2 < 2; j2++) {
            int krow = ks * 16 + (lane & 15);
            int ncol = wn + j2 * 16 + ((lane >> 4) << 3);
            uint32_t ad = xh + krow * 256 + ((((ncol >> 3) ^ (krow & 7)) << 4));
            ldsm4t(bfr[2 * j2][0], bfr[2 * j2][1], bfr[2 * j2 + 1][0], bfr[2 * j2 + 1][1], ad);
        }
        #pragma unroll
        for (int i = 0; i < 2; i++)
            #pragma unroll
            for (int j = 0; j < 4; j++)
                MMA16816(acc[i][j], a[i], bfr[j][0], bfr[j][1]);
    }
    #pragma unroll
    for (int i = 0; i < 2; i++)
        #pragma unroll
        for (int j = 0; j < 4; j++) {
            int c = wm + i * 16 + grp;
            int t = wn + j * 8 + 2 * tig;
            *(__half2*)&uP[((long)f * CCH + c) * TT + t0 + t] =
                __floats2half2_rn(acc[i][j][0] * scale, acc[i][j][1] * scale);
            *(__half2*)&uP[((long)f * CCH + c + 8) * TT + t0 + t] =
                __floats2half2_rn(acc[i][j][2] * scale, acc[i][j][3] * scale);
        }
}

// ======= S-GEMM: P~[t][t'] = exp( sum_d xrP[d][t] * uP[d][t'] ), + row sums ======
#define GS_SMEM (3 * 32768)
__global__ void __launch_bounds__(256, 2)
gemmS(const __half* __restrict__ Ag, const __half* __restrict__ Bg,
      __half* __restrict__ Pg, float* __restrict__ rs) {
    extern __shared__ char smraw[];
    const uint32_t sb = smem_u32(smraw);
    const int tid = threadIdx.x;
    const int m0 = blockIdx.y * 128, n0 = blockIdx.x * 128;
    Ag += (long)blockIdx.z * XBSTR + m0;
    Bg += (long)blockIdx.z * XBSTR + n0;
    Pg += (long)blockIdx.z * SBSTR;
    rs += (long)blockIdx.z * TT;
    const int niter = DDIM / 64;
    const int ldrow = tid >> 4, ldch = tid & 15;

    auto load_stage = [&](int c) {
        const uint32_t sa = sb + (c % 3) * 32768;
        const uint32_t sbf = sa + 16384;
        const __half* Ak = Ag + (long)c * 64 * TT;
        const __half* Bk = Bg + (long)c * 64 * TT;
        #pragma unroll
        for (int i = 0; i < 4; i++) {
            int row = ldrow + 16 * i;
            uint32_t xs = ((ldch ^ (row & 7)) << 4);
            cp16(sa + row * 256 + xs, Ak + (long)row * TT + ldch * 8);
        }
        #pragma unroll
        for (int i = 0; i < 4; i++) {
            int row = ldrow + 16 * i;
            uint32_t xs = ((ldch ^ (row & 7)) << 4);
            cp16(sbf + row * 256 + xs, Bk + (long)row * TT + ldch * 8);
        }
        cp_commit();
    };

    load_stage(0);
    load_stage(1);

    const int w = tid >> 5, lane = tid & 31, grp = lane >> 2, tig = lane & 3;
    const int wm = (w & 1) * 64, wn = (w >> 1) * 32;
    const int a_kl = (lane & 7) + ((lane & 16) ? 8 : 0);
    const int a_mo = ((lane & 8) ? 8 : 0);
    const int b_kl = (lane & 15);
    const int b_no = ((lane >> 4) << 3);
    float acc[4][4][4] = {};

    for (int c = 0; c < niter; c++) {
        cp_wait1();
        __syncthreads();
        if (c + 2 < niter) load_stage(c + 2); else cp_commit();

        const uint32_t sa = sb + (c % 3) * 32768;
        const uint32_t sbf = sa + 16384;
        #pragma unroll
        for (int ks = 0; ks < 4; ks++) {
            uint32_t a[4][4], b[4][2];
            const int krA = ks * 16 + a_kl;
            const int krB = ks * 16 + b_kl;
            #pragma unroll
            for (int i = 0; i < 4; i++) {
                int mcol = wm + i * 16 + a_mo;
                uint32_t ad = sa + krA * 256 + ((((mcol >> 3) ^ (krA & 7)) << 4));
                ldsm4t(a[i][0], a[i][1], a[i][2], a[i][3], ad);
            }
            #pragma unroll
            for (int j2 = 0; j2 < 2; j2++) {
                int ncol = wn + j2 * 16 + b_no;
                uint32_t ad = sbf + krB * 256 + ((((ncol >> 3) ^ (krB & 7)) << 4));
                ldsm4t(b[2 * j2][0], b[2 * j2][1], b[2 * j2 + 1][0], b[2 * j2 + 1][1], ad);
            }
            #pragma unroll
            for (int i = 0; i < 4; i++)
                #pragma unroll
                for (int j = 0; j < 4; j++)
                    MMA16816(acc[i][j], a[i], b[j][0], b[j][1]);
        }
    }

    // epilogue: exp (scores bounded; no max shift needed), write fp16, row sums
    #pragma unroll
    for (int i = 0; i < 4; i++) {
        float slo = 0.f, shi = 0.f;
        #pragma unroll
        for (int j = 0; j < 4; j++) {
            float e0 = __expf(acc[i][j][0]), e1 = __expf(acc[i][j][1]);
            float e2 = __expf(acc[i][j][2]), e3 = __expf(acc[i][j][3]);
            slo += e0 + e1; shi += e2 + e3;
            int row = m0 + wm + i * 16 + grp;
            int col = n0 + wn + j * 8 + 2 * tig;
            *(__half2*)&Pg[(long)row * TT + col]       = __floats2half2_rn(e0, e1);
            *(__half2*)&Pg[(long)(row + 8) * TT + col] = __floats2half2_rn(e2, e3);
        }
        slo += __shfl_xor_sync(~0u, slo, 1); slo += __shfl_xor_sync(~0u, slo, 2);
        shi += __shfl_xor_sync(~0u, shi, 1); shi += __shfl_xor_sync(~0u, shi, 2);
        if (tig == 0) {
            atomicAdd(&rs[m0 + wm + i * 16 + grp], slo);
            atomicAdd(&rs[m0 + wm + i * 16 + grp + 8], shi);
        }
    }
}

// ========== Z-GEMM + fused Wv mix + row-sum normalize ==========
// out[c][f][t] = (1/rs[t]) * sum_c' Wv[c][c'] * (P~ @ xrP^T)[t][f*64+c']
#define GZ_SMEM (3 * 32768 + 1024)
__global__ void __launch_bounds__(256, 2)
gemmZ(const __half* __restrict__ Ag, const __half* __restrict__ Bg,
      float* __restrict__ Cg, const float* __restrict__ Wv,
      const float* __restrict__ rs) {
    extern __shared__ char smraw[];
    const uint32_t sb = smem_u32(smraw);
    const int tid = threadIdx.x;
    const int m0 = blockIdx.y * 128, n0 = blockIdx.x * 128;
    Ag += (long)blockIdx.z * SBSTR + (long)m0 * TT;
    Bg += (long)blockIdx.z * XBSTR + (long)n0 * TT;
    Cg += (long)blockIdx.z * XBSTR;
    rs += (long)blockIdx.z * TT + m0;
    const int niter = TT / 64;
    const int ldrow = tid >> 3, ldch = tid & 7;

    auto load_stage = [&](int c) {
        const uint32_t sa = sb + (c % 3) * 32768;
        const uint32_t sbf = sa + 16384;
        const __half* Ak = Ag + (long)c * 64;
        const __half* Bk = Bg + (long)c * 64;
        #pragma unroll
        for (int i = 0; i < 4; i++) {
            int row = ldrow + 32 * i;
            uint32_t xs = ((ldch ^ (row & 7)) << 4);
            cp16(sa + row * 128 + xs, Ak + (long)row * TT + ldch * 8);
        }
        #pragma unroll
        for (int i = 0; i < 4; i++) {
            int row = ldrow + 32 * i;
            uint32_t xs = ((ldch ^ (row & 7)) << 4);
            cp16(sbf + row * 128 + xs, Bk + (long)row * TT + ldch * 8);
        }
        cp_commit();
    };

    load_stage(0);
    load_stage(1);

    const int w = tid >> 5, lane = tid & 31, grp = lane >> 2, tig = lane & 3;
    const int wm = (w & 1) * 64, wn = (w >> 1) * 32;
    // non-trans ldmatrix lane geometry
    const int a_rl = (lane & 7) + ((lane & 8) ? 8 : 0);   // row low for A
    const int a_ch = ((lane >> 4) & 1);                   // chunk hi for A
    const int b_rl = (lane & 7);
    const int b_jh = ((lane >> 4) & 1);                   // j offset for B
    const int b_ch = ((lane >> 3) & 1);                   // chunk hi for B
    float acc[4][4][4] = {};

    for (int c = 0; c < niter; c++) {
        cp_wait1();
        __syncthreads();
        if (c + 2 < niter) load_stage(c + 2); else cp_commit();

        const uint32_t sa = sb + (c % 3) * 32768;
        const uint32_t sbf = sa + 16384;
        #pragma unroll
        for (int ks = 0; ks < 4; ks++) {
            uint32_t a[4][4], b[4][2];
            #pragma unroll
            for (int i = 0; i < 4; i++) {
                int row = wm + i * 16 + a_rl;
                int ch = 2 * ks + a_ch;
                uint32_t ad = sa + row * 128 + (((ch ^ (row & 7)) << 4));
                ldsm4(a[i][0], a[i][1], a[i][2], a[i][3], ad);
            }
            #pragma unroll
            for (int j2 = 0; j2 < 2; j2++) {
                int row = wn + (2 * j2 + b_jh) * 8 + b_rl;
                int ch = 2 * ks + b_ch;
                uint32_t ad = sbf + row * 128 + (((ch ^ (row & 7)) << 4));
                ldsm4(b[2 * j2][0], b[2 * j2][1], b[2 * j2 + 1][0], b[2 * j2 + 1][1], ad);
            }
            #pragma unroll
            for (int i = 0; i < 4; i++)
                #pragma unroll
                for (int j = 0; j < 4; j++)
                    MMA16816(acc[i][j], a[i], b[j][0], b[j][1]);
        }
    }
    __syncthreads();

    // ---- fused epilogue ----
    const uint32_t zh0 = sb, zh1 = sb + 16384, wvs = sb + 2 * 16384;
    const uint32_t invs = sb + 3 * 32768;          // 128 floats
    if (tid < 128) {
        float r = rs[tid];
        asm volatile("st.shared.f32 [%0], %1;" :: "r"(invs + tid * 4), "f"(1.0f / r));
    }
    __syncthreads();

    #pragma unroll
    for (int i = 0; i < 4; i++) {
        int row = wm + i * 16 + grp;               // t (local)
        float iv0 = ldsf(invs + row * 4);
        float iv1 = ldsf(invs + (row + 8) * 4);
        #pragma unroll
        for (int j = 0; j < 4; j++) {
            int col = wn + j * 8 + 2 * tig;        // d' (local 0..127)
            uint32_t base = (col & 64) ? zh1 : zh0;
            int byt = (col & 63) * 2;
            uint32_t ad = base + row * 128 + ((((byt) >> 4) ^ (row & 7)) << 4) + (byt & 15);
            __half2 h0 = __floats2half2_rn(acc[i][j][0] * iv0, acc[i][j][1] * iv0);
            __half2 h1 = __floats2half2_rn(acc[i][j][2] * iv1, acc[i][j][3] * iv1);
            sts32(ad, *(uint32_t*)&h0);
            sts32(ad + 1024, *(uint32_t*)&h1);
        }
    }
    #pragma unroll
    for (int i = 0; i < 16; i++) {
        int idx = tid + 256 * i;
        int m = idx >> 6, k = idx & 63;
        sts16(wvs + m * 128 + (((k >> 3) ^ (m & 7)) << 4) + ((k & 7) * 2),
              __half_as_ushort(__float2half_rn(Wv[m * CCH + k])));
    }
    __syncthreads();

    const int fblk = w >> 2;
    const int w2 = w & 3;
    const int wm2 = (w2 & 1) * 32;                // c
    const int wn2 = (w2 >> 1) * 64;               // t
    const uint32_t zb = fblk ? zh1 : zh0;
    float oac[2][8][4] = {};
    #pragma unroll
    for (int ks = 0; ks < 4; ks++) {
        const int off = 4 * tig, ch0 = 2 * ks;
        const uint32_t x0 = ((ch0 ^ grp) << 4), x1 = (((ch0 + 1) ^ grp) << 4);
        uint32_t a[2][4], b[8][2];
        #pragma unroll
        for (int i = 0; i < 2; i++) {
            uint32_t b0 = wvs + (wm2 + i * 16 + grp) * 128 + off;
            uint32_t b1 = b0 + 1024;
            a[i][0] = lds32(b0 + x0); a[i][1] = lds32(b1 + x0);
            a[i][2] = lds32(b0 + x1); a[i][3] = lds32(b1 + x1);
        }
        #pragma unroll
        for (int j = 0; j < 8; j++) {
            uint32_t base = zb + (wn2 + j * 8 + grp) * 128 + off;
            b[j][0] = lds32(base + x0);
            b[j][1] = lds32(base + x1);
        }
        #pragma unroll
        for (int i = 0; i < 2; i++)
            #pragma unroll
            for (int j = 0; j < 8; j++)
                MMA16816(oac[i][j], a[i], b[j][0], b[j][1]);
    }
    const int f = (n0 >> 6) + fblk;
    #pragma unroll
    for (int i = 0; i < 2; i++)
        #pragma unroll
        for (int j = 0; j < 8; j++) {
            int cc = wm2 + i * 16 + grp;
            int t  = wn2 + j * 8 + 2 * tig;
            *(float2*)&Cg[((long)cc * FFREQ + f) * TT + m0 + t] =
                make_float2(oac[i][j][0], oac[i][j][1]);
            *(float2*)&Cg[((long)(cc + 8) * FFREQ + f) * TT + m0 + t] =
                make_float2(oac[i][j][2], oac[i][j][3]);
        }
}

extern "C" void kernel_launch(void* const* d_in, const int* in_sizes, int n_in,
                              void* d_out, int out_size) {
    (void)in_sizes; (void)n_in; (void)out_size;
    const float* x  = (const float*)d_in[0];
    const float* Wq = (const float*)d_in[1];
    const float* Wk = (const float*)d_in[2];
    const float* Wv = (const float*)d_in[3];
    float* out = (float*)d_out;

    __half *xrP, *uP, *P;
    float *RS;
    cudaGetSymbolAddress((void**)&xrP, g_xrP);
    cudaGetSymbolAddress((void**)&uP,  g_uP);
    cudaGetSymbolAddress((void**)&P,   g_p);
    cudaGetSymbolAddress((void**)&RS,  g_rs);

    cudaFuncSetAttribute(gemmS, cudaFuncAttributeMaxDynamicSharedMemorySize, GS_SMEM);
    cudaFuncSetAttribute(gemmZ, cudaFuncAttributeMaxDynamicSharedMemorySize, GZ_SMEM);

    // 1) G = Wq^T Wk; zero row sums
    compute_G_kernel<<<1, 256>>>(Wq, Wk);
    zero_rs_kernel<<<BATCH * TT / 256, 256>>>();

    // 2) prep: xrP + uP (x read once, no transposes)
    const float scale = 1.0f / sqrtf((float)DDIM);
    prep_kernel<<<dim3(TT / 128, FFREQ, BATCH), 256>>>(x, scale);

    // 3) P~ = exp(x^T u), row sums accumulated (no separate softmax pass)
    gemmS<<<dim3(TT / 128, TT / 128, BATCH), 256, GS_SMEM>>>(xrP, uP, P, RS);

    // 4) out = Wv ∘ (P~ @ xrP^T) / rs, fused epilogue, writes [B,C,F,T]
    gemmZ<<<dim3(DDIM / 128, TT / 128, BATCH), 256, GZ_SMEM>>>(P, xrP, out, Wv, RS);
}

// round 12
// speedup vs baseline: 1.0003x; 1.0003x over previous
#include <cuda_runtime.h>
#include <cuda_fp16.h>
#include <math.h>
#include <stdint.h>

// x: [B=16, C=64, F=40, T=512] fp32; Wq/Wk/Wv: [64,64] fp32
#define BATCH 16
#define CCH   64
#define FFREQ 40
#define TT    512
#define DDIM  2560
#define XBSTR ((long)DDIM * TT)
#define SBSTR ((long)TT * TT)

// -------- scratch --------
__device__ float  g_G  [CCH * CCH];
__device__ __half g_xrP[BATCH * DDIM * TT];    // h(x), [b][d=f*64+c][t]
__device__ __half g_uP [BATCH * DDIM * TT];    // h(scale * G∘x), [b][d][t]
__device__ __half g_p  [BATCH * TT * TT];      // P~ = exp(S), unnormalized
__device__ float  g_rs [BATCH * TT];           // row sums of P~

// ---------------- helpers ----------------
__device__ __forceinline__ uint32_t smem_u32(const void* p) {
    uint32_t a;
    asm("{ .reg .u64 t; cvta.to.shared.u64 t, %1; cvt.u32.u64 %0, t; }" : "=r"(a) : "l"(p));
    return a;
}
__device__ __forceinline__ void cp16(uint32_t sdst, const void* g) {
    asm volatile("cp.async.cg.shared.global [%0], [%1], 16;" :: "r"(sdst), "l"(g));
}
__device__ __forceinline__ void cp_commit() { asm volatile("cp.async.commit_group;"); }
__device__ __forceinline__ void cp_wait1()  { asm volatile("cp.async.wait_group 1;"); }
__device__ __forceinline__ uint32_t lds32(uint32_t a) {
    uint32_t v; asm volatile("ld.shared.b32 %0, [%1];" : "=r"(v) : "r"(a)); return v;
}
__device__ __forceinline__ float ldsf(uint32_t a) {
    float v; asm volatile("ld.shared.f32 %0, [%1];" : "=f"(v) : "r"(a)); return v;
}
__device__ __forceinline__ void sts16(uint32_t a, uint16_t v) {
    asm volatile("st.shared.u16 [%0], %1;" :: "r"(a), "h"(v));
}
__device__ __forceinline__ void sts32(uint32_t a, uint32_t v) {
    asm volatile("st.shared.b32 [%0], %1;" :: "r"(a), "r"(v));
}
__device__ __forceinline__ void sts64(uint32_t a, uint32_t x, uint32_t y) {
    asm volatile("st.shared.v2.b32 [%0], {%1, %2};" :: "r"(a), "r"(x), "r"(y));
}
__device__ __forceinline__ void ldsm4t(uint32_t& r0, uint32_t& r1, uint32_t& r2,
                                       uint32_t& r3, uint32_t addr) {
    asm volatile("ldmatrix.sync.aligned.m8n8.x4.trans.shared.b16 {%0,%1,%2,%3}, [%4];"
                 : "=r"(r0), "=r"(r1), "=r"(r2), "=r"(r3) : "r"(addr));
}
__device__ __forceinline__ void ldsm4(uint32_t& r0, uint32_t& r1, uint32_t& r2,
                                      uint32_t& r3, uint32_t addr) {
    asm volatile("ldmatrix.sync.aligned.m8n8.x4.shared.b16 {%0,%1,%2,%3}, [%4];"
                 : "=r"(r0), "=r"(r1), "=r"(r2), "=r"(r3) : "r"(addr));
}

#define MMA16816(d, a, b0, b1)                                                   \
    asm volatile(                                                                \
        "mma.sync.aligned.m16n8k16.row.col.f32.f16.f16.f32 "                     \
        "{%0,%1,%2,%3}, {%4,%5,%6,%7}, {%8,%9}, {%0,%1,%2,%3};"                  \
        : "+f"((d)[0]), "+f"((d)[1]), "+f"((d)[2]), "+f"((d)[3])                 \
        : "r"((a)[0]), "r"((a)[1]), "r"((a)[2]), "r"((a)[3]), "r"(b0), "r"(b1))

// ============================ G = Wq^T Wk ============================
__global__ void compute_G_kernel(const float* __restrict__ Wq,
                                 const float* __restrict__ Wk) {
    __shared__ float sq[CCH * CCH], sk[CCH * CCH];
    int tid = threadIdx.x;
    for (int i = tid; i < CCH * CCH; i += blockDim.x) { sq[i] = Wq[i]; sk[i] = Wk[i]; }
    __syncthreads();
    for (int i = tid; i < CCH * CCH; i += blockDim.x) {
        int c = i / CCH, cp = i % CCH;
        float acc = 0.f;
        #pragma unroll 16
        for (int o = 0; o < CCH; o++) acc += sq[o * CCH + c] * sk[o * CCH + cp];
        g_G[i] = acc;
    }
}

// -------- zero row sums --------
__global__ void zero_rs_kernel() {
    g_rs[blockIdx.x * 256 + threadIdx.x] = 0.f;
}

// ======== prep: x -> xrP [d][t] AND uP = h(scale * G@x) [d][t] ========
__global__ void __launch_bounds__(256)
prep_kernel(const float* __restrict__ x, float scale) {
    __shared__ __align__(128) char sm[24576];
    const uint32_t xh = smem_u32(sm);            // [c'][t] half, 256B rows, swz16
    const uint32_t gg = xh + 16384;              // [c][c'] half, 128B rows, swz16
    const int t0 = blockIdx.x * 128;
    const int f  = blockIdx.y;
    const int b  = blockIdx.z;
    const float* xb = x + (long)b * XBSTR;
    __half* xrP = g_xrP + (long)b * XBSTR;
    __half* uP  = g_uP  + (long)b * XBSTR;
    const int tid = threadIdx.x;

    #pragma unroll
    for (int i = 0; i < 8; i++) {
        int idx = tid + 256 * i;
        int c = idx >> 5, q = idx & 31;
        float4 v = *(const float4*)&xb[((long)c * FFREQ + f) * TT + t0 + q * 4];
        __half2 h0 = __floats2half2_rn(v.x, v.y);
        __half2 h1 = __floats2half2_rn(v.z, v.w);
        *(uint2*)&xrP[((long)f * CCH + c) * TT + t0 + q * 4] =
            make_uint2(*(uint32_t*)&h0, *(uint32_t*)&h1);
        uint32_t ad = xh + c * 256 + ((((q >> 1) ^ (c & 7)) << 4)) + ((q & 1) * 8);
        sts64(ad, *(uint32_t*)&h0, *(uint32_t*)&h1);
    }
    #pragma unroll
    for (int i = 0; i < 16; i++) {
        int idx = tid + 256 * i;
        int m = idx >> 6, k = idx & 63;
        sts16(gg + m * 128 + (((k >> 3) ^ (m & 7)) << 4) + ((k & 7) * 2),
              __half_as_ushort(__float2half_rn(g_G[m * CCH + k])));
    }
    __syncthreads();

    const int w = tid >> 5, lane = tid & 31, grp = lane >> 2, tig = lane & 3;
    const int wm = (w & 1) * 32, wn = (w >> 1) * 32;
    float acc[2][4][4] = {};
    #pragma unroll
    for (int ks = 0; ks < 4; ks++) {
        const int off = 4 * tig, ch0 = 2 * ks;
        const uint32_t x0 = ((ch0 ^ grp) << 4), x1 = (((ch0 + 1) ^ grp) << 4);
        uint32_t a[2][4], bfr[4][2];
        #pragma unroll
        for (int i = 0; i < 2; i++) {
            uint32_t b0 = gg + (wm + i * 16 + grp) * 128 + off;
            uint32_t b1 = b0 + 1024;
            a[i][0] = lds32(b0 + x0); a[i][1] = lds32(b1 + x0);
            a[i][2] = lds32(b0 + x1); a[i][3] = lds32(b1 + x1);
        }
        #pragma unroll
        for (int j2 = 0; j2 < 2; j2++) {
            int krow = ks * 16 + (lane & 15);
            int ncol = wn + j2 * 16 + ((lane >> 4) << 3);
            uint32_t ad = xh + krow * 256 + ((((ncol >> 3) ^ (krow & 7)) << 4));
            ldsm4t(bfr[2 * j2][0], bfr[2 * j2][1], bfr[2 * j2 + 1][0], bfr[2 * j2 + 1][1], ad);
        }
        #pragma unroll
        for (int i = 0; i < 2; i++)
            #pragma unroll
            for (int j = 0; j < 4; j++)
                MMA16816(acc[i][j], a[i], bfr[j][0], bfr[j][1]);
    }
    #pragma unroll
    for (int i = 0; i < 2; i++)
        #pragma unroll
        for (int j = 0; j < 4; j++) {
            int c = wm + i * 16 + grp;
            int t = wn + j * 8 + 2 * tig;
            *(__half2*)&uP[((long)f * CCH + c) * TT + t0 + t] =
                __floats2half2_rn(acc[i][j][0] * scale, acc[i][j][1] * scale);
            *(__half2*)&uP[((long)f * CCH + c + 8) * TT + t0 + t] =
                __floats2half2_rn(acc[i][j][2] * scale, acc[i][j][3] * scale);
        }
}

// ======= S-GEMM: P~[t][t'] = exp( sum_d xrP[d][t] * uP[d][t'] ), + row sums ======
#define GS_SMEM (3 * 32768)
__global__ void __launch_bounds__(256, 2)
gemmS(const __half* __restrict__ Ag, const __half* __restrict__ Bg,
      __half* __restrict__ Pg, float* __restrict__ rs) {
    extern __shared__ char smraw[];
    const uint32_t sb = smem_u32(smraw);
    const int tid = threadIdx.x;
    const int m0 = blockIdx.y * 128, n0 = blockIdx.x * 128;
    Ag += (long)blockIdx.z * XBSTR + m0;
    Bg += (long)blockIdx.z * XBSTR + n0;
    Pg += (long)blockIdx.z * SBSTR;
    rs += (long)blockIdx.z * TT;
    const int niter = DDIM / 64;
    const int ldrow = tid >> 4, ldch = tid & 15;

    auto load_stage = [&](int c) {
        const uint32_t sa = sb + (c % 3) * 32768;
        const uint32_t sbf = sa + 16384;
        const __half* Ak = Ag + (long)c * 64 * TT;
        const __half* Bk = Bg + (long)c * 64 * TT;
        #pragma unroll
        for (int i = 0; i < 4; i++) {
            int row = ldrow + 16 * i;
            uint32_t xs = ((ldch ^ (row & 7)) << 4);
            cp16(sa + row * 256 + xs, Ak + (long)row * TT + ldch * 8);
        }
        #pragma unroll
        for (int i = 0; i < 4; i++) {
            int row = ldrow + 16 * i;
            uint32_t xs = ((ldch ^ (row & 7)) << 4);
            cp16(sbf + row * 256 + xs, Bk + (long)row * TT + ldch * 8);
        }
        cp_commit();
    };

    load_stage(0);
    load_stage(1);

    const int w = tid >> 5, lane = tid & 31, grp = lane >> 2, tig = lane & 3;
    const int wm = (w & 1) * 64, wn = (w >> 1) * 32;
    const int a_kl = (lane & 7) + ((lane & 16) ? 8 : 0);
    const int a_mo = ((lane & 8) ? 8 : 0);
    const int b_kl = (lane & 15);
    const int b_no = ((lane >> 4) << 3);
    float acc[4][4][4] = {};

    for (int c = 0; c < niter; c++) {
        cp_wait1();
        __syncthreads();
        if (c + 2 < niter) load_stage(c + 2); else cp_commit();

        const uint32_t sa = sb + (c % 3) * 32768;
        const uint32_t sbf = sa + 16384;
        #pragma unroll
        for (int ks = 0; ks < 4; ks++) {
            uint32_t a[4][4], b[4][2];
            const int krA = ks * 16 + a_kl;
            const int krB = ks * 16 + b_kl;
            #pragma unroll
            for (int i = 0; i < 4; i++) {
                int mcol = wm + i * 16 + a_mo;
                uint32_t ad = sa + krA * 256 + ((((mcol >> 3) ^ (krA & 7)) << 4));
                ldsm4t(a[i][0], a[i][1], a[i][2], a[i][3], ad);
            }
            #pragma unroll
            for (int j2 = 0; j2 < 2; j2++) {
                int ncol = wn + j2 * 16 + b_no;
                uint32_t ad = sbf + krB * 256 + ((((ncol >> 3) ^ (krB & 7)) << 4));
                ldsm4t(b[2 * j2][0], b[2 * j2][1], b[2 * j2 + 1][0], b[2 * j2 + 1][1], ad);
            }
            #pragma unroll
            for (int i = 0; i < 4; i++)
                #pragma unroll
                for (int j = 0; j < 4; j++)
                    MMA16816(acc[i][j], a[i], b[j][0], b[j][1]);
        }
    }

    // epilogue: exp (scores bounded; no max shift needed), write fp16, row sums
    #pragma unroll
    for (int i = 0; i < 4; i++) {
        float slo = 0.f, shi = 0.f;
        #pragma unroll
        for (int j = 0; j < 4; j++) {
            float e0 = __expf(acc[i][j][0]), e1 = __expf(acc[i][j][1]);
            float e2 = __expf(acc[i][j][2]), e3 = __expf(acc[i][j][3]);
            slo += e0 + e1; shi += e2 + e3;
            int row = m0 + wm + i * 16 + grp;
            int col = n0 + wn + j * 8 + 2 * tig;
            *(__half2*)&Pg[(long)row * TT + col]       = __floats2half2_rn(e0, e1);
            *(__half2*)&Pg[(long)(row + 8) * TT + col] = __floats2half2_rn(e2, e3);
        }
        slo += __shfl_xor_sync(~0u, slo, 1); slo += __shfl_xor_sync(~0u, slo, 2);
        shi += __shfl_xor_sync(~0u, shi, 1); shi += __shfl_xor_sync(~0u, shi, 2);
        if (tig == 0) {
            atomicAdd(&rs[m0 + wm + i * 16 + grp], slo);
            atomicAdd(&rs[m0 + wm + i * 16 + grp + 8], shi);
        }
    }
}

// ========== Z-GEMM + fused Wv mix + row-sum normalize ==========
// out[c][f][t] = (1/rs[t]) * sum_c' Wv[c][c'] * (P~ @ xrP^T)[t][f*64+c']
#define GZ_SMEM (3 * 32768 + 1024)
__global__ void __launch_bounds__(256, 2)
gemmZ(const __half* __restrict__ Ag, const __half* __restrict__ Bg,
      float* __restrict__ Cg, const float* __restrict__ Wv,
      const float* __restrict__ rs) {
    extern __shared__ char smraw[];
    const uint32_t sb = smem_u32(smraw);
    const int tid = threadIdx.x;
    const int m0 = blockIdx.y * 128, n0 = blockIdx.x * 128;
    Ag += (long)blockIdx.z * SBSTR + (long)m0 * TT;
    Bg += (long)blockIdx.z * XBSTR + (long)n0 * TT;
    Cg += (long)blockIdx.z * XBSTR;
    rs += (long)blockIdx.z * TT + m0;
    const int niter = TT / 64;
    const int ldrow = tid >> 3, ldch = tid & 7;

    auto load_stage = [&](int c) {
        const uint32_t sa = sb + (c % 3) * 32768;
        const uint32_t sbf = sa + 16384;
        const __half* Ak = Ag + (long)c * 64;
        const __half* Bk = Bg + (long)c * 64;
        #pragma unroll
        for (int i = 0; i < 4; i++) {
            int row = ldrow + 32 * i;
            uint32_t xs = ((ldch ^ (row & 7)) << 4);
            cp16(sa + row * 128 + xs, Ak + (long)row * TT + ldch * 8);
        }
        #pragma unroll
        for (int i = 0; i < 4; i++) {
            int row = ldrow + 32 * i;
            uint32_t xs = ((ldch ^ (row & 7)) << 4);
            cp16(sbf + row * 128 + xs, Bk + (long)row * TT + ldch * 8);
        }
        cp_commit();
    };

    load_stage(0);
    load_stage(1);

    const int w = tid >> 5, lane = tid & 31, grp = lane >> 2, tig = lane & 3;
    const int wm = (w & 1) * 64, wn = (w >> 1) * 32;
    // non-trans ldmatrix lane geometry
    const int a_rl = (lane & 7) + ((lane & 8) ? 8 : 0);   // row low for A
    const int a_ch = ((lane >> 4) & 1);                   // chunk hi for A
    const int b_rl = (lane & 7);
    const int b_jh = ((lane >> 4) & 1);                   // j offset for B
    const int b_ch = ((lane >> 3) & 1);                   // chunk hi for B
    float acc[4][4][4] = {};

    for (int c = 0; c < niter; c++) {
        cp_wait1();
        __syncthreads();
        if (c + 2 < niter) load_stage(c + 2); else cp_commit();

        const uint32_t sa = sb + (c % 3) * 32768;
        const uint32_t sbf = sa + 16384;
        #pragma unroll
        for (int ks = 0; ks < 4; ks++) {
            uint32_t a[4][4], b[4][2];
            #pragma unroll
            for (int i = 0; i < 4; i++) {
                int row = wm + i * 16 + a_rl;
                int ch = 2 * ks + a_ch;
                uint32_t ad = sa + row * 128 + (((ch ^ (row & 7)) << 4));
                ldsm4(a[i][0], a[i][1], a[i][2], a[i][3], ad);
            }
            #pragma unroll
            for (int j2 = 0; j2 < 2; j2++) {
                int row = wn + (2 * j2 + b_jh) * 8 + b_rl;
                int ch = 2 * ks + b_ch;
                uint32_t ad = sbf + row * 128 + (((ch ^ (row & 7)) << 4));
                ldsm4(b[2 * j2][0], b[2 * j2][1], b[2 * j2 + 1][0], b[2 * j2 + 1][1], ad);
            }
            #pragma unroll
            for (int i = 0; i < 4; i++)
                #pragma unroll
                for (int j = 0; j < 4; j++)
                    MMA16816(acc[i][j], a[i], b[j][0], b[j][1]);
        }
    }
    __syncthreads();

    // ---- fused epilogue ----
    const uint32_t zh0 = sb, zh1 = sb + 16384, wvs = sb + 2 * 16384;
    const uint32_t invs = sb + 3 * 32768;          // 128 floats
    if (tid < 128) {
        float r = rs[tid];
        asm volatile("st.shared.f32 [%0], %1;" :: "r"(invs + tid * 4), "f"(1.0f / r));
    }
    __syncthreads();

    #pragma unroll
    for (int i = 0; i < 4; i++) {
        int row = wm + i * 16 + grp;               // t (local)
        float iv0 = ldsf(invs + row * 4);
        float iv1 = ldsf(invs + (row + 8) * 4);
        #pragma unroll
        for (int j = 0; j < 4; j++) {
            int col = wn + j * 8 + 2 * tig;        // d' (local 0..127)
            uint32_t base = (col & 64) ? zh1 : zh0;
            int byt = (col & 63) * 2;
            uint32_t ad = base + row * 128 + ((((byt) >> 4) ^ (row & 7)) << 4) + (byt & 15);
            __half2 h0 = __floats2half2_rn(acc[i][j][0] * iv0, acc[i][j][1] * iv0);
            __half2 h1 = __floats2half2_rn(acc[i][j][2] * iv1, acc[i][j][3] * iv1);
            sts32(ad, *(uint32_t*)&h0);
            sts32(ad + 1024, *(uint32_t*)&h1);
        }
    }
    #pragma unroll
    for (int i = 0; i < 16; i++) {
        int idx = tid + 256 * i;
        int m = idx >> 6, k = idx & 63;
        sts16(wvs + m * 128 + (((k >> 3) ^ (m & 7)) << 4) + ((k & 7) * 2),
              __half_as_ushort(__float2half_rn(Wv[m * CCH + k])));
    }
    __syncthreads();

    const int fblk = w >> 2;
    const int w2 = w & 3;
    const int wm2 = (w2 & 1) * 32;                // c
    const int wn2 = (w2 >> 1) * 64;               // t
    const uint32_t zb = fblk ? zh1 : zh0;
    float oac[2][8][4] = {};
    #pragma unroll
    for (int ks = 0; ks < 4; ks++) {
        const int off = 4 * tig, ch0 = 2 * ks;
        const uint32_t x0 = ((ch0 ^ grp) << 4), x1 = (((ch0 + 1) ^ grp) << 4);
        uint32_t a[2][4], b[8][2];
        #pragma unroll
        for (int i = 0; i < 2; i++) {
            uint32_t b0 = wvs + (wm2 + i * 16 + grp) * 128 + off;
            uint32_t b1 = b0 + 1024;
            a[i][0] = lds32(b0 + x0); a[i][1] = lds32(b1 + x0);
            a[i][2] = lds32(b0 + x1); a[i][3] = lds32(b1 + x1);
        }
        #pragma unroll
        for (int j = 0; j < 8; j++) {
            uint32_t base = zb + (wn2 + j * 8 + grp) * 128 + off;
            b[j][0] = lds32(base + x0);
            b[j][1] = lds32(base + x1);
        }
        #pragma unroll
        for (int i = 0; i < 2; i++)
            #pragma unroll
            for (int j = 0; j < 8; j++)
                MMA16816(oac[i][j], a[i], b[j][0], b[j][1]);
    }
    const int f = (n0 >> 6) + fblk;
    #pragma unroll
    for (int i = 0; i < 2; i++)
        #pragma unroll
        for (int j = 0; j < 8; j++) {
            int cc = wm2 + i * 16 + grp;
            int t  = wn2 + j * 8 + 2 * tig;
            *(float2*)&Cg[((long)cc * FFREQ + f) * TT + m0 + t] =
                make_float2(oac[i][j][0], oac[i][j][1]);
            *(float2*)&Cg[((long)(cc + 8) * FFREQ + f) * TT + m0 + t] =
                make_float2(oac[i][j][2], oac[i][j][3]);
        }
}

extern "C" void kernel_launch(void* const* d_in, const int* in_sizes, int n_in,
                              void* d_out, int out_size) {
    (void)in_sizes; (void)n_in; (void)out_size;
    const float* x  = (const float*)d_in[0];
    const float* Wq = (const float*)d_in[1];
    const float* Wk = (const float*)d_in[2];
    const float* Wv = (const float*)d_in[3];
    float* out = (float*)d_out;

    __half *xrP, *uP, *P;
    float *RS;
    cudaGetSymbolAddress((void**)&xrP, g_xrP);
    cudaGetSymbolAddress((void**)&uP,  g_uP);
    cudaGetSymbolAddress((void**)&P,   g_p);
    cudaGetSymbolAddress((void**)&RS,  g_rs);

    cudaFuncSetAttribute(gemmS, cudaFuncAttributeMaxDynamicSharedMemorySize, GS_SMEM);
    cudaFuncSetAttribute(gemmZ, cudaFuncAttributeMaxDynamicSharedMemorySize, GZ_SMEM);

    // 1) G = Wq^T Wk; zero row sums
    compute_G_kernel<<<1, 256>>>(Wq, Wk);
    zero_rs_kernel<<<BATCH * TT / 256, 256>>>();

    // 2) prep: xrP + uP (x read once, no transposes)
    const float scale = 1.0f / sqrtf((float)DDIM);
    prep_kernel<<<dim3(TT / 128, FFREQ, BATCH), 256>>>(x, scale);

    // 3) P~ = exp(x^T u), row sums accumulated (no separate softmax pass)
    gemmS<<<dim3(TT / 128, TT / 128, BATCH), 256, GS_SMEM>>>(xrP, uP, P, RS);

    // 4) out = Wv ∘ (P~ @ xrP^T) / rs, fused epilogue, writes [B,C,F,T]
    gemmZ<<<dim3(DDIM / 128, TT / 128, BATCH), 256, GZ_SMEM>>>(P, xrP, out, Wv, RS);
}

// round 13
// speedup vs baseline: 1.0009x; 1.0005x over previous
#include <cuda_runtime.h>
#include <cuda_fp16.h>
#include <math.h>
#include <stdint.h>

// x: [B=16, C=64, F=40, T=512] fp32; Wq/Wk/Wv: [64,64] fp32
#define BATCH 16
#define CCH   64
#define FFREQ 40
#define TT    512
#define DDIM  2560
#define XBSTR ((long)DDIM * TT)
#define SBSTR ((long)TT * TT)

// -------- scratch --------
__device__ float  g_G  [CCH * CCH];
__device__ __half g_xrP[BATCH * DDIM * TT];    // h(x), [b][d=f*64+c][t]
__device__ __half g_uP [BATCH * DDIM * TT];    // h(scale * G∘x), [b][d][t]
__device__ __half g_p  [BATCH * TT * TT];      // P~ = exp(S), unnormalized
__device__ float  g_rs [BATCH * TT];           // row sums of P~

// ---------------- helpers ----------------
__device__ __forceinline__ uint32_t smem_u32(const void* p) {
    uint32_t a;
    asm("{ .reg .u64 t; cvta.to.shared.u64 t, %1; cvt.u32.u64 %0, t; }" : "=r"(a) : "l"(p));
    return a;
}
__device__ __forceinline__ void cp16(uint32_t sdst, const void* g) {
    asm volatile("cp.async.cg.shared.global [%0], [%1], 16;" :: "r"(sdst), "l"(g));
}
__device__ __forceinline__ void cp_commit() { asm volatile("cp.async.commit_group;"); }
__device__ __forceinline__ void cp_wait1()  { asm volatile("cp.async.wait_group 1;"); }
__device__ __forceinline__ uint32_t lds32(uint32_t a) {
    uint32_t v; asm volatile("ld.shared.b32 %0, [%1];" : "=r"(v) : "r"(a)); return v;
}
__device__ __forceinline__ float ldsf(uint32_t a) {
    float v; asm volatile("ld.shared.f32 %0, [%1];" : "=f"(v) : "r"(a)); return v;
}
__device__ __forceinline__ void sts16(uint32_t a, uint16_t v) {
    asm volatile("st.shared.u16 [%0], %1;" :: "r"(a), "h"(v));
}
__device__ __forceinline__ void sts32(uint32_t a, uint32_t v) {
    asm volatile("st.shared.b32 [%0], %1;" :: "r"(a), "r"(v));
}
__device__ __forceinline__ void sts64(uint32_t a, uint32_t x, uint32_t y) {
    asm volatile("st.shared.v2.b32 [%0], {%1, %2};" :: "r"(a), "r"(x), "r"(y));
}
__device__ __forceinline__ void ldsm4t(uint32_t& r0, uint32_t& r1, uint32_t& r2,
                                       uint32_t& r3, uint32_t addr) {
    asm volatile("ldmatrix.sync.aligned.m8n8.x4.trans.shared.b16 {%0,%1,%2,%3}, [%4];"
                 : "=r"(r0), "=r"(r1), "=r"(r2), "=r"(r3) : "r"(addr));
}
__device__ __forceinline__ void ldsm4(uint32_t& r0, uint32_t& r1, uint32_t& r2,
                                      uint32_t& r3, uint32_t addr) {
    asm volatile("ldmatrix.sync.aligned.m8n8.x4.shared.b16 {%0,%1,%2,%3}, [%4];"
                 : "=r"(r0), "=r"(r1), "=r"(r2), "=r"(r3) : "r"(addr));
}

#define MMA16816(d, a, b0, b1)                                                   \
    asm volatile(                                                                \
        "mma.sync.aligned.m16n8k16.row.col.f32.f16.f16.f32 "                     \
        "{%0,%1,%2,%3}, {%4,%5,%6,%7}, {%8,%9}, {%0,%1,%2,%3};"                  \
        : "+f"((d)[0]), "+f"((d)[1]), "+f"((d)[2]), "+f"((d)[3])                 \
        : "r"((a)[0]), "r"((a)[1]), "r"((a)[2]), "r"((a)[3]), "r"(b0), "r"(b1))

// ============================ G = Wq^T Wk ============================
__global__ void compute_G_kernel(const float* __restrict__ Wq,
                                 const float* __restrict__ Wk) {
    __shared__ float sq[CCH * CCH], sk[CCH * CCH];
    int tid = threadIdx.x;
    for (int i = tid; i < CCH * CCH; i += blockDim.x) { sq[i] = Wq[i]; sk[i] = Wk[i]; }
    __syncthreads();
    for (int i = tid; i < CCH * CCH; i += blockDim.x) {
        int c = i / CCH, cp = i % CCH;
        float acc = 0.f;
        #pragma unroll 16
        for (int o = 0; o < CCH; o++) acc += sq[o * CCH + c] * sk[o * CCH + cp];
        g_G[i] = acc;
    }
}

// -------- zero row sums --------
__global__ void zero_rs_kernel() {
    g_rs[blockIdx.x * 256 + threadIdx.x] = 0.f;
}

// ======== prep: x -> xrP [d][t] AND uP = h(scale * G@x) [d][t] ========
__global__ void __launch_bounds__(256)
prep_kernel(const float* __restrict__ x, float scale) {
    __shared__ __align__(128) char sm[24576];
    const uint32_t xh = smem_u32(sm);            // [c'][t] half, 256B rows, swz16
    const uint32_t gg = xh + 16384;              // [c][c'] half, 128B rows, swz16
    const int t0 = blockIdx.x * 128;
    const int f  = blockIdx.y;
    const int b  = blockIdx.z;
    const float* xb = x + (long)b * XBSTR;
    __half* xrP = g_xrP + (long)b * XBSTR;
    __half* uP  = g_uP  + (long)b * XBSTR;
    const int tid = threadIdx.x;

    #pragma unroll
    for (int i = 0; i < 8; i++) {
        int idx = tid + 256 * i;
        int c = idx >> 5, q = idx & 31;
        float4 v = *(const float4*)&xb[((long)c * FFREQ + f) * TT + t0 + q * 4];
        __half2 h0 = __floats2half2_rn(v.x, v.y);
        __half2 h1 = __floats2half2_rn(v.z, v.w);
        *(uint2*)&xrP[((long)f * CCH + c) * TT + t0 + q * 4] =
            make_uint2(*(uint32_t*)&h0, *(uint32_t*)&h1);
        uint32_t ad = xh + c * 256 + ((((q >> 1) ^ (c & 7)) << 4)) + ((q & 1) * 8);
        sts64(ad, *(uint32_t*)&h0, *(uint32_t*)&h1);
    }
    #pragma unroll
    for (int i = 0; i < 16; i++) {
        int idx = tid + 256 * i;
        int m = idx >> 6, k = idx & 63;
        sts16(gg + m * 128 + (((k >> 3) ^ (m & 7)) << 4) + ((k & 7) * 2),
              __half_as_ushort(__float2half_rn(g_G[m * CCH + k])));
    }
    __syncthreads();

    const int w = tid >> 5, lane = tid & 31, grp = lane >> 2, tig = lane & 3;
    const int wm = (w & 1) * 32, wn = (w >> 1) * 32;
    float acc[2][4][4] = {};
    #pragma unroll
    for (int ks = 0; ks < 4; ks++) {
        const int off = 4 * tig, ch0 = 2 * ks;
        const uint32_t x0 = ((ch0 ^ grp) << 4), x1 = (((ch0 + 1) ^ grp) << 4);
        uint32_t a[2][4], bfr[4][2];
        #pragma unroll
        for (int i = 0; i < 2; i++) {
            uint32_t b0 = gg + (wm + i * 16 + grp) * 128 + off;
            uint32_t b1 = b0 + 1024;
            a[i][0] = lds32(b0 + x0); a[i][1] = lds32(b1 + x0);
            a[i][2] = lds32(b0 + x1); a[i][3] = lds32(b1 + x1);
        }
        #pragma unroll
        for (int j2 = 0; j2 < 2; j2++) {
            int krow = ks * 16 + (lane & 15);
            int ncol = wn + j2 * 16 + ((lane >> 4) << 3);
            uint32_t ad = xh + krow * 256 + ((((ncol >> 3) ^ (krow & 7)) << 4));
            ldsm4t(bfr[2 * j2][0], bfr[2 * j2][1], bfr[2 * j2 + 1][0], bfr[2 * j2 + 1][1], ad);
        }
        #pragma unroll
        for (int i = 0; i < 2; i++)
            #pragma unroll
            for (int j = 0; j < 4; j++)
                MMA16816(acc[i][j], a[i], bfr[j][0], bfr[j][1]);
    }
    #pragma unroll
    for (int i = 0; i < 2; i++)
        #pragma unroll
        for (int j = 0; j < 4; j++) {
            int c = wm + i * 16 + grp;
            int t = wn + j * 8 + 2 * tig;
            *(__half2*)&uP[((long)f * CCH + c) * TT + t0 + t] =
                __floats2half2_rn(acc[i][j][0] * scale, acc[i][j][1] * scale);
            *(__half2*)&uP[((long)f * CCH + c + 8) * TT + t0 + t] =
                __floats2half2_rn(acc[i][j][2] * scale, acc[i][j][3] * scale);
        }
}

// ======= S-GEMM: P~[t][t'] = exp( sum_d xrP[d][t] * uP[d][t'] ), + row sums ======
#define GS_SMEM (3 * 32768)
__global__ void __launch_bounds__(256, 2)
gemmS(const __half* __restrict__ Ag, const __half* __restrict__ Bg,
      __half* __restrict__ Pg, float* __restrict__ rs) {
    extern __shared__ char smraw[];
    const uint32_t sb = smem_u32(smraw);
    const int tid = threadIdx.x;
    const int m0 = blockIdx.y * 128, n0 = blockIdx.x * 128;
    Ag += (long)blockIdx.z * XBSTR + m0;
    Bg += (long)blockIdx.z * XBSTR + n0;
    Pg += (long)blockIdx.z * SBSTR;
    rs += (long)blockIdx.z * TT;
    const int niter = DDIM / 64;
    const int ldrow = tid >> 4, ldch = tid & 15;

    auto load_stage = [&](int c) {
        const uint32_t sa = sb + (c % 3) * 32768;
        const uint32_t sbf = sa + 16384;
        const __half* Ak = Ag + (long)c * 64 * TT;
        const __half* Bk = Bg + (long)c * 64 * TT;
        #pragma unroll
        for (int i = 0; i < 4; i++) {
            int row = ldrow + 16 * i;
            uint32_t xs = ((ldch ^ (row & 7)) << 4);
            cp16(sa + row * 256 + xs, Ak + (long)row * TT + ldch * 8);
        }
        #pragma unroll
        for (int i = 0; i < 4; i++) {
            int row = ldrow + 16 * i;
            uint32_t xs = ((ldch ^ (row & 7)) << 4);
            cp16(sbf + row * 256 + xs, Bk + (long)row * TT + ldch * 8);
        }
        cp_commit();
    };

    load_stage(0);
    load_stage(1);

    const int w = tid >> 5, lane = tid & 31, grp = lane >> 2, tig = lane & 3;
    const int wm = (w & 1) * 64, wn = (w >> 1) * 32;
    const int a_kl = (lane & 7) + ((lane & 16) ? 8 : 0);
    const int a_mo = ((lane & 8) ? 8 : 0);
    const int b_kl = (lane & 15);
    const int b_no = ((lane >> 4) << 3);
    float acc[4][4][4] = {};

    for (int c = 0; c < niter; c++) {
        cp_wait1();
        __syncthreads();
        if (c + 2 < niter) load_stage(c + 2); else cp_commit();

        const uint32_t sa = sb + (c % 3) * 32768;
        const uint32_t sbf = sa + 16384;
        #pragma unroll
        for (int ks = 0; ks < 4; ks++) {
            uint32_t a[4][4], b[4][2];
            const int krA = ks * 16 + a_kl;
            const int krB = ks * 16 + b_kl;
            #pragma unroll
            for (int i = 0; i < 4; i++) {
                int mcol = wm + i * 16 + a_mo;
                uint32_t ad = sa + krA * 256 + ((((mcol >> 3) ^ (krA & 7)) << 4));
                ldsm4t(a[i][0], a[i][1], a[i][2], a[i][3], ad);
            }
            #pragma unroll
            for (int j2 = 0; j2 < 2; j2++) {
                int ncol = wn + j2 * 16 + b_no;
                uint32_t ad = sbf + krB * 256 + ((((ncol >> 3) ^ (krB & 7)) << 4));
                ldsm4t(b[2 * j2][0], b[2 * j2][1], b[2 * j2 + 1][0], b[2 * j2 + 1][1], ad);
            }
            #pragma unroll
            for (int i = 0; i < 4; i++)
                #pragma unroll
                for (int j = 0; j < 4; j++)
                    MMA16816(acc[i][j], a[i], b[j][0], b[j][1]);
        }
    }

    // epilogue: exp (scores bounded; no max shift needed), write fp16, row sums
    #pragma unroll
    for (int i = 0; i < 4; i++) {
        float slo = 0.f, shi = 0.f;
        #pragma unroll
        for (int j = 0; j < 4; j++) {
            float e0 = __expf(acc[i][j][0]), e1 = __expf(acc[i][j][1]);
            float e2 = __expf(acc[i][j][2]), e3 = __expf(acc[i][j][3]);
            slo += e0 + e1; shi += e2 + e3;
            int row = m0 + wm + i * 16 + grp;
            int col = n0 + wn + j * 8 + 2 * tig;
            *(__half2*)&Pg[(long)row * TT + col]       = __floats2half2_rn(e0, e1);
            *(__half2*)&Pg[(long)(row + 8) * TT + col] = __floats2half2_rn(e2, e3);
        }
        slo += __shfl_xor_sync(~0u, slo, 1); slo += __shfl_xor_sync(~0u, slo, 2);
        shi += __shfl_xor_sync(~0u, shi, 1); shi += __shfl_xor_sync(~0u, shi, 2);
        if (tig == 0) {
            atomicAdd(&rs[m0 + wm + i * 16 + grp], slo);
            atomicAdd(&rs[m0 + wm + i * 16 + grp + 8], shi);
        }
    }
}

// ========== Z-GEMM + fused Wv mix + row-sum normalize ==========
// out[c][f][t] = (1/rs[t]) * sum_c' Wv[c][c'] * (P~ @ xrP^T)[t][f*64+c']
#define GZ_SMEM (3 * 32768 + 1024)
__global__ void __launch_bounds__(256, 2)
gemmZ(const __half* __restrict__ Ag, const __half* __restrict__ Bg,
      float* __restrict__ Cg, const float* __restrict__ Wv,
      const float* __restrict__ rs) {
    extern __shared__ char smraw[];
    const uint32_t sb = smem_u32(smraw);
    const int tid = threadIdx.x;
    const int m0 = blockIdx.y * 128, n0 = blockIdx.x * 128;
    Ag += (long)blockIdx.z * SBSTR + (long)m0 * TT;
    Bg += (long)blockIdx.z * XBSTR + (long)n0 * TT;
    Cg += (long)blockIdx.z * XBSTR;
    rs += (long)blockIdx.z * TT + m0;
    const int niter = TT / 64;
    const int ldrow = tid >> 3, ldch = tid & 7;

    auto load_stage = [&](int c) {
        const uint32_t sa = sb + (c % 3) * 32768;
        const uint32_t sbf = sa + 16384;
        const __half* Ak = Ag + (long)c * 64;
        const __half* Bk = Bg + (long)c * 64;
        #pragma unroll
        for (int i = 0; i < 4; i++) {
            int row = ldrow + 32 * i;
            uint32_t xs = ((ldch ^ (row & 7)) << 4);
            cp16(sa + row * 128 + xs, Ak + (long)row * TT + ldch * 8);
        }
        #pragma unroll
        for (int i = 0; i < 4; i++) {
            int row = ldrow + 32 * i;
            uint32_t xs = ((ldch ^ (row & 7)) << 4);
            cp16(sbf + row * 128 + xs, Bk + (long)row * TT + ldch * 8);
        }
        cp_commit();
    };

    load_stage(0);
    load_stage(1);

    const int w = tid >> 5, lane = tid & 31, grp = lane >> 2, tig = lane & 3;
    const int wm = (w & 1) * 64, wn = (w >> 1) * 32;
    // non-trans ldmatrix lane geometry
    const int a_rl = (lane & 7) + ((lane & 8) ? 8 : 0);   // row low for A
    const int a_ch = ((lane >> 4) & 1);                   // chunk hi for A
    const int b_rl = (lane & 7);
    const int b_jh = ((lane >> 4) & 1);                   // j offset for B
    const int b_ch = ((lane >> 3) & 1);                   // chunk hi for B
    float acc[4][4][4] = {};

    for (int c = 0; c < niter; c++) {
        cp_wait1();
        __syncthreads();
        if (c + 2 < niter) load_stage(c + 2); else cp_commit();

        const uint32_t sa = sb + (c % 3) * 32768;
        const uint32_t sbf = sa + 16384;
        #pragma unroll
        for (int ks = 0; ks < 4; ks++) {
            uint32_t a[4][4], b[4][2];
            #pragma unroll
            for (int i = 0; i < 4; i++) {
                int row = wm + i * 16 + a_rl;
                int ch = 2 * ks + a_ch;
                uint32_t ad = sa + row * 128 + (((ch ^ (row & 7)) << 4));
                ldsm4(a[i][0], a[i][1], a[i][2], a[i][3], ad);
            }
            #pragma unroll
            for (int j2 = 0; j2 < 2; j2++) {
                int row = wn + (2 * j2 + b_jh) * 8 + b_rl;
                int ch = 2 * ks + b_ch;
                uint32_t ad = sbf + row * 128 + (((ch ^ (row & 7)) << 4));
                ldsm4(b[2 * j2][0], b[2 * j2][1], b[2 * j2 + 1][0], b[2 * j2 + 1][1], ad);
            }
            #pragma unroll
            for (int i = 0; i < 4; i++)
                #pragma unroll
                for (int j = 0; j < 4; j++)
                    MMA16816(acc[i][j], a[i], b[j][0], b[j][1]);
        }
    }
    __syncthreads();

    // ---- fused epilogue ----
    const uint32_t zh0 = sb, zh1 = sb + 16384, wvs = sb + 2 * 16384;
    const uint32_t invs = sb + 3 * 32768;          // 128 floats
    if (tid < 128) {
        float r = rs[tid];
        asm volatile("st.shared.f32 [%0], %1;" :: "r"(invs + tid * 4), "f"(1.0f / r));
    }
    __syncthreads();

    #pragma unroll
    for (int i = 0; i < 4; i++) {
        int row = wm + i * 16 + grp;               // t (local)
        float iv0 = ldsf(invs + row * 4);
        float iv1 = ldsf(invs + (row + 8) * 4);
        #pragma unroll
        for (int j = 0; j < 4; j++) {
            int col = wn + j * 8 + 2 * tig;        // d' (local 0..127)
            uint32_t base = (col & 64) ? zh1 : zh0;
            int byt = (col & 63) * 2;
            uint32_t ad = base + row * 128 + ((((byt) >> 4) ^ (row & 7)) << 4) + (byt & 15);
            __half2 h0 = __floats2half2_rn(acc[i][j][0] * iv0, acc[i][j][1] * iv0);
            __half2 h1 = __floats2half2_rn(acc[i][j][2] * iv1, acc[i][j][3] * iv1);
            sts32(ad, *(uint32_t*)&h0);
            sts32(ad + 1024, *(uint32_t*)&h1);
        }
    }
    #pragma unroll
    for (int i = 0; i < 16; i++) {
        int idx = tid + 256 * i;
        int m = idx >> 6, k = idx & 63;
        sts16(wvs + m * 128 + (((k >> 3) ^ (m & 7)) << 4) + ((k & 7) * 2),
              __half_as_ushort(__float2half_rn(Wv[m * CCH + k])));
    }
    __syncthreads();

    const int fblk = w >> 2;
    const int w2 = w & 3;
    const int wm2 = (w2 & 1) * 32;                // c
    const int wn2 = (w2 >> 1) * 64;               // t
    const uint32_t zb = fblk ? zh1 : zh0;
    float oac[2][8][4] = {};
    #pragma unroll
    for (int ks = 0; ks < 4; ks++) {
        const int off = 4 * tig, ch0 = 2 * ks;
        const uint32_t x0 = ((ch0 ^ grp) << 4), x1 = (((ch0 + 1) ^ grp) << 4);
        uint32_t a[2][4], b[8][2];
        #pragma unroll
        for (int i = 0; i < 2; i++) {
            uint32_t b0 = wvs + (wm2 + i * 16 + grp) * 128 + off;
            uint32_t b1 = b0 + 1024;
            a[i][0] = lds32(b0 + x0); a[i][1] = lds32(b1 + x0);
            a[i][2] = lds32(b0 + x1); a[i][3] = lds32(b1 + x1);
        }
        #pragma unroll
        for (int j = 0; j < 8; j++) {
            uint32_t base = zb + (wn2 + j * 8 + grp) * 128 + off;
            b[j][0] = lds32(base + x0);
            b[j][1] = lds32(base + x1);
        }
        #pragma unroll
        for (int i = 0; i < 2; i++)
            #pragma unroll
            for (int j = 0; j < 8; j++)
                MMA16816(oac[i][j], a[i], b[j][0], b[j][1]);
    }
    const int f = (n0 >> 6) + fblk;
    #pragma unroll
    for (int i = 0; i < 2; i++)
        #pragma unroll
        for (int j = 0; j < 8; j++) {
            int cc = wm2 + i * 16 + grp;
            int t  = wn2 + j * 8 + 2 * tig;
            *(float2*)&Cg[((long)cc * FFREQ + f) * TT + m0 + t] =
                make_float2(oac[i][j][0], oac[i][j][1]);
            *(float2*)&Cg[((long)(cc + 8) * FFREQ + f) * TT + m0 + t] =
                make_float2(oac[i][j][2], oac[i][j][3]);
        }
}

extern "C" void kernel_launch(void* const* d_in, const int* in_sizes, int n_in,
                              void* d_out, int out_size) {
    (void)in_sizes; (void)n_in; (void)out_size;
    const float* x  = (const float*)d_in[0];
    const float* Wq = (const float*)d_in[1];
    const float* Wk = (const float*)d_in[2];
    const float* Wv = (const float*)d_in[3];
    float* out = (float*)d_out;

    __half *xrP, *uP, *P;
    float *RS;
    cudaGetSymbolAddress((void**)&xrP, g_xrP);
    cudaGetSymbolAddress((void**)&uP,  g_uP);
    cudaGetSymbolAddress((void**)&P,   g_p);
    cudaGetSymbolAddress((void**)&RS,  g_rs);

    cudaFuncSetAttribute(gemmS, cudaFuncAttributeMaxDynamicSharedMemorySize, GS_SMEM);
    cudaFuncSetAttribute(gemmZ, cudaFuncAttributeMaxDynamicSharedMemorySize, GZ_SMEM);

    // 1) G = Wq^T Wk; zero row sums
    compute_G_kernel<<<1, 256>>>(Wq, Wk);
    zero_rs_kernel<<<BATCH * TT / 256, 256>>>();

    // 2) prep: xrP + uP (x read once, no transposes)
    const float scale = 1.0f / sqrtf((float)DDIM);
    prep_kernel<<<dim3(TT / 128, FFREQ, BATCH), 256>>>(x, scale);

    // 3) P~ = exp(x^T u), row sums accumulated (no separate softmax pass)
    gemmS<<<dim3(TT / 128, TT / 128, BATCH), 256, GS_SMEM>>>(xrP, uP, P, RS);

    // 4) out = Wv ∘ (P~ @ xrP^T) / rs, fused epilogue, writes [B,C,F,T]
    gemmZ<<<dim3(DDIM / 128, TT / 128, BATCH), 256, GZ_SMEM>>>(P, xrP, out, Wv, RS);
}